// round 3
// baseline (speedup 1.0000x reference)
#include <cuda_runtime.h>

// Problem constants (fixed by the reference)
#define NN   50000
#define EE   1600000
#define BB   128
#define FXs  16
#define FEs  4
#define FINs 20
#define MMs  64
#define HHs  32
#define MHs  2048   // M*H
#define KKs  64     // padded K (60 real: diag_part | sum_of_rows | sum_of_cols)
#define NTILES 391
#define NPAD (NTILES*128)  // 50048

// ---------------- scratch (device globals: no allocation allowed) ----------------
__device__ __align__(16) float g_rows[NN*FEs];
__device__ __align__(16) float g_cols[NN*FEs];
__device__ int   g_winner[NN];
__device__ int   g_cnt[BB];
__device__ float g_fact[BB];
__device__ float g_gd[BB*FINs];     // segsum(diag_part)
__device__ float g_gc[BB*FINs];     // segsum(sum_of_cols)  (already * fact_n)
__device__ __align__(16) float g_A[NPAD*KKs];   // per-node features, K-padded
__device__ __align__(16) float g_W[KKs*MHs];    // transposed weights [k][mh]
__device__ __align__(16) float g_Cg[BB*MHs];    // per-graph offset (+bias_equiv)
__device__ float g_acc[BB*MHs];                 // segsum(relu(...)) accumulator

__device__ __forceinline__ float4 f4s(float4 v, float s) {
    return make_float4(v.x*s, v.y*s, v.z*s, v.w*s);
}

// ---------------- init: zero scratch, winner=-1, zero A padding rows ----------------
__global__ void k_init() {
    int idx = blockIdx.x * 256 + threadIdx.x;           // grid covers 262144
    if (idx < NN*FEs) { g_rows[idx] = 0.f; g_cols[idx] = 0.f; }
    if (idx < NN)      g_winner[idx] = -1;
    if (idx < BB*MHs)  g_acc[idx] = 0.f;
    if (idx < BB*FINs) { g_gd[idx] = 0.f; g_gc[idx] = 0.f; }
    if (idx < BB)      g_cnt[idx] = 0;
    if (idx < (NPAD-NN)*KKs) g_A[NN*KKs + idx] = 0.f;
}

// ---------------- per-graph node counts ----------------
__global__ void k_count(const int* __restrict__ batch) {
    int n = blockIdx.x * 256 + threadIdx.x;
    if (n < NN) atomicAdd(&g_cnt[batch[n]], 1);
}
__global__ void k_fact() {
    int b = threadIdx.x;
    if (b < BB) g_fact[b] = 1.0f / (float)g_cnt[b];
}

// ---------------- weight transpose: W[k][mh] (k: 20 diag | 20 rows | 20 cols | 4 zero) ----
__global__ void k_wprep(const float* __restrict__ ke) {
    int idx = blockIdx.x * 256 + threadIdx.x;           // KKs*MHs = 131072
    if (idx >= KKs*MHs) return;
    int k  = idx >> 11;
    int mh = idx & 2047;
    int m = mh >> 5, h = mh & 31;
    float v = 0.f;
    if (k < 60) {
        int bsel, f;
        if (k < 20)      { bsel = 0; f = k;      }
        else if (k < 40) { bsel = 2; f = k - 20; }
        else             { bsel = 3; f = k - 40; }
        v = ke[((m*5 + bsel)*HHs + h)*FINs + f];
    }
    g_W[idx] = v;
}

// ---------------- edge scatter: rows/cols sums + last-write-wins self-loop ----------------
__global__ void k_edge(const int* __restrict__ ei, const float* __restrict__ ea) {
    int e = blockIdx.x * 256 + threadIdx.x;
    if (e >= EE) return;
    int s = ei[e], d = ei[EE + e];
    float4 a = ((const float4*)ea)[e];
    float* rs = g_rows + s*4;
    atomicAdd(rs+0, a.x); atomicAdd(rs+1, a.y); atomicAdd(rs+2, a.z); atomicAdd(rs+3, a.w);
    float* cs = g_cols + d*4;
    atomicAdd(cs+0, a.x); atomicAdd(cs+1, a.y); atomicAdd(cs+2, a.z); atomicAdd(cs+3, a.w);
    if (s == d) atomicMax(&g_winner[s], e);
}

// ---------------- per-node basis build + per-graph partial sums ----------------
__global__ void k_node(const float* __restrict__ x, const float* __restrict__ ea,
                       const int* __restrict__ batch) {
    int n = blockIdx.x * 256 + threadIdx.x;
    if (n >= NN) return;
    int b = batch[n];
    float fac = g_fact[b];
    const float4* xr = (const float4*)(x + (size_t)n*FXs);
    float4 x0 = xr[0], x1 = xr[1], x2 = xr[2], x3 = xr[3];
    int w = g_winner[n];
    float4 de = make_float4(0.f,0.f,0.f,0.f);
    if (w >= 0) de = ((const float4*)ea)[w];
    float4 r = ((const float4*)g_rows)[n];
    float4 c = ((const float4*)g_cols)[n];
    float4 x0f = f4s(x0,fac), x1f = f4s(x1,fac), x2f = f4s(x2,fac), x3f = f4s(x3,fac);
    float4 rf = f4s(r,fac), cf = f4s(c,fac);

    float4* A = (float4*)(g_A + (size_t)n*KKs);
    A[0]=x0;  A[1]=x1;  A[2]=x2;  A[3]=x3;  A[4]=de;      // diag_part (unscaled)
    A[5]=x0f; A[6]=x1f; A[7]=x2f; A[8]=x3f; A[9]=rf;      // sum_of_rows * fact
    A[10]=x0f;A[11]=x1f;A[12]=x2f;A[13]=x3f;A[14]=cf;     // sum_of_cols * fact
    A[15]=make_float4(0.f,0.f,0.f,0.f);

    float* gd = g_gd + b*FINs;
    atomicAdd(gd+0,x0.x); atomicAdd(gd+1,x0.y); atomicAdd(gd+2,x0.z); atomicAdd(gd+3,x0.w);
    atomicAdd(gd+4,x1.x); atomicAdd(gd+5,x1.y); atomicAdd(gd+6,x1.z); atomicAdd(gd+7,x1.w);
    atomicAdd(gd+8,x2.x); atomicAdd(gd+9,x2.y); atomicAdd(gd+10,x2.z); atomicAdd(gd+11,x2.w);
    atomicAdd(gd+12,x3.x); atomicAdd(gd+13,x3.y); atomicAdd(gd+14,x3.z); atomicAdd(gd+15,x3.w);
    atomicAdd(gd+16,de.x); atomicAdd(gd+17,de.y); atomicAdd(gd+18,de.z); atomicAdd(gd+19,de.w);
    float* gc = g_gc + b*FINs;
    atomicAdd(gc+0,x0f.x); atomicAdd(gc+1,x0f.y); atomicAdd(gc+2,x0f.z); atomicAdd(gc+3,x0f.w);
    atomicAdd(gc+4,x1f.x); atomicAdd(gc+5,x1f.y); atomicAdd(gc+6,x1f.z); atomicAdd(gc+7,x1f.w);
    atomicAdd(gc+8,x2f.x); atomicAdd(gc+9,x2f.y); atomicAdd(gc+10,x2f.z); atomicAdd(gc+11,x2f.w);
    atomicAdd(gc+12,x3f.x); atomicAdd(gc+13,x3f.y); atomicAdd(gc+14,x3f.z); atomicAdd(gc+15,x3f.w);
    atomicAdd(gc+16,cf.x); atomicAdd(gc+17,cf.y); atomicAdd(gc+18,cf.z); atomicAdd(gc+19,cf.w);
}

// ---------------- per-graph offset Cg = bias + fact*sdp·K1 + fact^2*sa·K4 ----------------
__global__ void k_cg(const float* __restrict__ ke, const float* __restrict__ be) {
    int idx = blockIdx.x * 256 + threadIdx.x;            // BB*MHs = 262144
    if (idx >= BB*MHs) return;
    int b = idx >> 11;
    int mh = idx & 2047;
    int m = mh >> 5, h = mh & 31;
    float fac = g_fact[b];
    const float* k1 = ke + ((m*5 + 1)*HHs + h)*FINs;
    const float* k4 = ke + ((m*5 + 4)*HHs + h)*FINs;
    const float* gd = g_gd + b*FINs;
    const float* gc = g_gc + b*FINs;
    float s1 = 0.f, s4 = 0.f;
    #pragma unroll
    for (int f = 0; f < FINs; f++) { s1 += gd[f]*k1[f]; s4 += gc[f]*k4[f]; }
    g_Cg[idx] = be[mh] + fac*s1 + fac*fac*s4;
}

// ---------------- fused GEMM + bias/Cg + ReLU + segment reduction ----------------
// grid (16 mh-tiles, 391 node-tiles), 256 threads, 128x128 tile, K=64 in two 32-halves.
__global__ __launch_bounds__(256, 2) void k_gemm(const int* __restrict__ batch) {
    __shared__ __align__(16) float As[32][132];
    __shared__ __align__(16) float Ws[32][132];
    __shared__ float red[2][128];
    int tid = threadIdx.x;
    int tx = tid & 15, ty = tid >> 4;
    int nb = blockIdx.y * 128;
    int mb = blockIdx.x * 128;

    float acc[8][8];
    #pragma unroll
    for (int i = 0; i < 8; i++)
        #pragma unroll
        for (int j = 0; j < 8; j++) acc[i][j] = 0.f;

    const float* Abase = g_A + (size_t)nb * KKs;
    #pragma unroll
    for (int s = 0; s < 2; s++) {
        int ks = s * 32;
        // load A tile, transpose to [k][node]
        {
            int rowA = tid >> 1, seg = tid & 1;
            const float4* src = (const float4*)(Abase + rowA*KKs + ks + seg*16);
            #pragma unroll
            for (int q = 0; q < 4; q++) {
                float4 v = src[q];
                int c = seg*16 + q*4;
                As[c+0][rowA] = v.x; As[c+1][rowA] = v.y;
                As[c+2][rowA] = v.z; As[c+3][rowA] = v.w;
            }
        }
        // load W tile [k][mh] straight
        {
            int kw = tid >> 3; int j0 = (tid & 7) * 4;
            const float4* src = (const float4*)(g_W + (size_t)(ks+kw)*MHs + mb) + j0;
            float4* dst = (float4*)(&Ws[kw][0]) + j0;
            #pragma unroll
            for (int q = 0; q < 4; q++) dst[q] = src[q];
        }
        __syncthreads();
        #pragma unroll 8
        for (int k = 0; k < 32; k++) {
            float4 a0 = *(const float4*)&As[k][ty*8];
            float4 a1 = *(const float4*)&As[k][ty*8+4];
            float4 w0 = *(const float4*)&Ws[k][tx*8];
            float4 w1 = *(const float4*)&Ws[k][tx*8+4];
            float av[8] = {a0.x,a0.y,a0.z,a0.w,a1.x,a1.y,a1.z,a1.w};
            float wv[8] = {w0.x,w0.y,w0.z,w0.w,w1.x,w1.y,w1.z,w1.w};
            #pragma unroll
            for (int i = 0; i < 8; i++)
                #pragma unroll
                for (int j = 0; j < 8; j++)
                    acc[i][j] += av[i] * wv[j];
        }
        __syncthreads();
    }

    // epilogue: relu(acc + Cg[g][mh]) reduced per-graph (<=2 graphs per tile)
    int g0 = batch[nb];
    float part[2][8];
    #pragma unroll
    for (int s = 0; s < 2; s++)
        #pragma unroll
        for (int j = 0; j < 8; j++) part[s][j] = 0.f;

    #pragma unroll
    for (int i = 0; i < 8; i++) {
        int n = nb + ty*8 + i;
        if (n < NN) {
            int g = batch[n];
            int s = (g != g0) ? 1 : 0;
            const float* cg = g_Cg + (size_t)g*MHs + mb + tx*8;
            #pragma unroll
            for (int j = 0; j < 8; j++) {
                float v = acc[i][j] + cg[j];
                part[s][j] += fmaxf(v, 0.f);
            }
        }
    }

    red[tid >> 7][tid & 127] = 0.f;
    __syncthreads();
    #pragma unroll
    for (int s = 0; s < 2; s++)
        #pragma unroll
        for (int j = 0; j < 8; j++)
            if (part[s][j] != 0.f) atomicAdd(&red[s][tx*8 + j], part[s][j]);
    __syncthreads();
    {
        int s = tid >> 7, c = tid & 127;
        int g = g0 + s;
        float v = red[s][c];
        if (g < BB && v != 0.f) atomicAdd(&g_acc[(size_t)g*MHs + mb + c], v);
    }
}

// ---------------- final: out[b][m] = sum_h (acc*fact - relu(bias_eq)) * kinv ----------------
__global__ void k_final(const float* __restrict__ be, const float* __restrict__ kinv,
                        float* __restrict__ out) {
    int b = blockIdx.x;
    int m = threadIdx.x;
    float fac = g_fact[b];
    const float* acc = g_acc + (size_t)b*MHs + m*HHs;
    const float* beh = be + m*HHs;
    const float* kv  = kinv + m*HHs;
    float s = 0.f;
    #pragma unroll
    for (int h = 0; h < HHs; h++)
        s += (acc[h]*fac - fmaxf(beh[h], 0.f)) * kv[h];
    out[b*MMs + m] = s;
}

extern "C" void kernel_launch(void* const* d_in, const int* in_sizes, int n_in,
                              void* d_out, int out_size) {
    const float* x    = (const float*)d_in[0];
    const float* ea   = (const float*)d_in[1];
    const float* ke   = (const float*)d_in[2];
    const float* kinv = (const float*)d_in[3];
    const float* be   = (const float*)d_in[4];
    // d_in[5] = bias_inv: cancels in psi - zerograph
    const int* ei     = (const int*)d_in[6];
    const int* batch  = (const int*)d_in[7];
    float* out = (float*)d_out;

    k_init<<<1024, 256>>>();
    k_count<<<(NN+255)/256, 256>>>(batch);
    k_fact<<<1, BB>>>();
    k_wprep<<<(KKs*MHs)/256, 256>>>(ke);
    k_edge<<<(EE+255)/256, 256>>>(ei, ea);
    k_node<<<(NN+255)/256, 256>>>(x, ea, batch);
    k_cg<<<(BB*MHs)/256, 256>>>(ke, be);
    dim3 gg(MHs/128, NTILES);
    k_gemm<<<gg, 256>>>(batch);
    k_final<<<BB, MMs>>>(be, kinv, out);
}

// round 5
// speedup vs baseline: 1.7321x; 1.7321x over previous
#include <cuda_runtime.h>
#include <cuda_bf16.h>
#include <cstdint>

// Problem constants (fixed by the reference)
#define NN   50000
#define EE   1600000
#define BB   128
#define FXs  16
#define FEs  4
#define FINs 20
#define MMs  64
#define HHs  32
#define MHs  2048   // M*H
#define KKs  64     // padded K (60 real: diag_part | sum_of_rows | sum_of_cols)
#define NTILES 391
#define NPAD (NTILES*128)  // 50048

// smem layout for k_mm (dynamic, 73728 B)
// phase 1 (operands): 4 tiles of 128 rows x 144B (72 bf16, padded from 64)
#define SM_A_HI 0
#define SM_A_LO 18432
#define SM_W_HI 36864
#define SM_W_LO 55296
#define TPITCHB 144
// phase 2 (epilogue, reuses same memory): flg@0 (512B), cgs@512 (1KB), buf@2048
#define BUFW 132
#define SMEM_BYTES 73728

// ---------------- scratch (device globals: no allocation allowed) ----------------
__device__ __align__(16) float g_rows[NN*FEs];
__device__ __align__(16) float g_cols[NN*FEs];
__device__ int   g_winner[NN];
__device__ int   g_cnt[BB];
__device__ float g_fact[BB];
__device__ float g_gd[BB*FINs];
__device__ float g_gc[BB*FINs];
__device__ __align__(16) __nv_bfloat16 g_Ahi[NPAD*KKs];
__device__ __align__(16) __nv_bfloat16 g_Alo[NPAD*KKs];
__device__ __align__(16) __nv_bfloat16 g_Whi[MHs*KKs];   // [mh][k], K-major
__device__ __align__(16) __nv_bfloat16 g_Wlo[MHs*KKs];
__device__ __align__(16) float g_Cg[BB*MHs];             // per-graph offset (+bias_equiv)
__device__ float g_acc[BB*MHs];                          // segsum(relu(...)) accumulator

__device__ __forceinline__ float4 f4s(float4 v, float s) {
    return make_float4(v.x*s, v.y*s, v.z*s, v.w*s);
}
__device__ __forceinline__ uint32_t pk2(__nv_bfloat16 a, __nv_bfloat16 b) {
    __nv_bfloat162 t = __halves2bfloat162(a, b);
    return *reinterpret_cast<uint32_t*>(&t);
}
__device__ __forceinline__ uint32_t s2u(const void* p) {
    uint32_t a;
    asm("{ .reg .u64 t; cvta.to.shared.u64 t, %1; cvt.u32.u64 %0, t; }" : "=r"(a) : "l"(p));
    return a;
}
#define LDM4(r, addr) \
    asm volatile("ldmatrix.sync.aligned.m8n8.x4.shared.b16 {%0,%1,%2,%3}, [%4];" \
        : "=r"((r)[0]), "=r"((r)[1]), "=r"((r)[2]), "=r"((r)[3]) : "r"(addr))

__device__ __forceinline__ void mma16816(float* c, const uint32_t* a,
                                         uint32_t b0, uint32_t b1) {
    asm volatile(
        "mma.sync.aligned.m16n8k16.row.col.f32.bf16.bf16.f32 "
        "{%0,%1,%2,%3}, {%4,%5,%6,%7}, {%8,%9}, {%0,%1,%2,%3};"
        : "+f"(c[0]), "+f"(c[1]), "+f"(c[2]), "+f"(c[3])
        : "r"(a[0]), "r"(a[1]), "r"(a[2]), "r"(a[3]), "r"(b0), "r"(b1));
}

// ---------------- init ----------------
__global__ void k_init() {
    int idx = blockIdx.x * 256 + threadIdx.x;           // grid covers 262144
    if (idx < NN*FEs) { g_rows[idx] = 0.f; g_cols[idx] = 0.f; }
    if (idx < NN)      g_winner[idx] = -1;
    if (idx < BB*MHs)  g_acc[idx] = 0.f;
    if (idx < BB*FINs) { g_gd[idx] = 0.f; g_gc[idx] = 0.f; }
    if (idx < BB)      g_cnt[idx] = 0;
    if (idx < (NPAD-NN)*KKs) {                          // zero A padding rows
        g_Ahi[NN*KKs + idx] = __float2bfloat16(0.f);
        g_Alo[NN*KKs + idx] = __float2bfloat16(0.f);
    }
}

// ---------------- per-graph node counts ----------------
__global__ void k_count(const int* __restrict__ batch) {
    int n = blockIdx.x * 256 + threadIdx.x;
    if (n < NN) atomicAdd(&g_cnt[batch[n]], 1);
}
__global__ void k_fact() {
    int b = threadIdx.x;
    if (b < BB) g_fact[b] = 1.0f / (float)g_cnt[b];
}

// ---------------- weight prep: W[mh][k] as bf16 hi/lo ----------------
__global__ void k_wprep(const float* __restrict__ ke) {
    int idx = blockIdx.x * 256 + threadIdx.x;           // MHs*KKs = 131072
    if (idx >= MHs*KKs) return;
    int mh = idx >> 6, k = idx & 63;
    int m = mh >> 5, h = mh & 31;
    float v = 0.f;
    if (k < 60) {
        int bsel, f;
        if (k < 20)      { bsel = 0; f = k;      }
        else if (k < 40) { bsel = 2; f = k - 20; }
        else             { bsel = 3; f = k - 40; }
        v = ke[((m*5 + bsel)*HHs + h)*FINs + f];
    }
    __nv_bfloat16 hi = __float2bfloat16(v);
    g_Whi[idx] = hi;
    g_Wlo[idx] = __float2bfloat16(v - __bfloat162float(hi));
}

// ---------------- edge scatter ----------------
__global__ void k_edge(const int* __restrict__ ei, const float* __restrict__ ea) {
    int e = blockIdx.x * 256 + threadIdx.x;
    if (e >= EE) return;
    int s = ei[e], d = ei[EE + e];
    float4 a = ((const float4*)ea)[e];
    float* rs = g_rows + s*4;
    atomicAdd(rs+0, a.x); atomicAdd(rs+1, a.y); atomicAdd(rs+2, a.z); atomicAdd(rs+3, a.w);
    float* cs = g_cols + d*4;
    atomicAdd(cs+0, a.x); atomicAdd(cs+1, a.y); atomicAdd(cs+2, a.z); atomicAdd(cs+3, a.w);
    if (s == d) atomicMax(&g_winner[s], e);
}

// ---------------- per-node basis build (bf16 hi/lo) + per-graph partial sums ----------------
__global__ void k_node(const float* __restrict__ x, const float* __restrict__ ea,
                       const int* __restrict__ batch) {
    int n = blockIdx.x * 256 + threadIdx.x;
    if (n >= NN) return;
    int b = batch[n];
    float fac = g_fact[b];
    const float4* xr = (const float4*)(x + (size_t)n*FXs);
    float4 x0 = xr[0], x1 = xr[1], x2 = xr[2], x3 = xr[3];
    int w = g_winner[n];
    float4 de = make_float4(0.f,0.f,0.f,0.f);
    if (w >= 0) de = ((const float4*)ea)[w];
    float4 r = ((const float4*)g_rows)[n];
    float4 c = ((const float4*)g_cols)[n];
    float4 x0f = f4s(x0,fac), x1f = f4s(x1,fac), x2f = f4s(x2,fac), x3f = f4s(x3,fac);
    float4 rf = f4s(r,fac), cf = f4s(c,fac);

    uint32_t hib[32], lob[32];
    float4 vals[16] = { x0, x1, x2, x3, de,
                        x0f, x1f, x2f, x3f, rf,
                        x0f, x1f, x2f, x3f, cf,
                        make_float4(0.f,0.f,0.f,0.f) };
    #pragma unroll
    for (int i = 0; i < 16; i++) {
        float4 v = vals[i];
        __nv_bfloat16 ax = __float2bfloat16(v.x), ay = __float2bfloat16(v.y);
        __nv_bfloat16 az = __float2bfloat16(v.z), aw = __float2bfloat16(v.w);
        hib[2*i]   = pk2(ax, ay);
        hib[2*i+1] = pk2(az, aw);
        lob[2*i]   = pk2(__float2bfloat16(v.x - __bfloat162float(ax)),
                         __float2bfloat16(v.y - __bfloat162float(ay)));
        lob[2*i+1] = pk2(__float2bfloat16(v.z - __bfloat162float(az)),
                         __float2bfloat16(v.w - __bfloat162float(aw)));
    }
    uint4* dh = (uint4*)g_Ahi + (size_t)n*8;
    uint4* dl = (uint4*)g_Alo + (size_t)n*8;
    #pragma unroll
    for (int i = 0; i < 8; i++) { dh[i] = ((uint4*)hib)[i]; dl[i] = ((uint4*)lob)[i]; }

    float* gd = g_gd + b*FINs;
    atomicAdd(gd+0,x0.x); atomicAdd(gd+1,x0.y); atomicAdd(gd+2,x0.z); atomicAdd(gd+3,x0.w);
    atomicAdd(gd+4,x1.x); atomicAdd(gd+5,x1.y); atomicAdd(gd+6,x1.z); atomicAdd(gd+7,x1.w);
    atomicAdd(gd+8,x2.x); atomicAdd(gd+9,x2.y); atomicAdd(gd+10,x2.z); atomicAdd(gd+11,x2.w);
    atomicAdd(gd+12,x3.x); atomicAdd(gd+13,x3.y); atomicAdd(gd+14,x3.z); atomicAdd(gd+15,x3.w);
    atomicAdd(gd+16,de.x); atomicAdd(gd+17,de.y); atomicAdd(gd+18,de.z); atomicAdd(gd+19,de.w);
    float* gc = g_gc + b*FINs;
    atomicAdd(gc+0,x0f.x); atomicAdd(gc+1,x0f.y); atomicAdd(gc+2,x0f.z); atomicAdd(gc+3,x0f.w);
    atomicAdd(gc+4,x1f.x); atomicAdd(gc+5,x1f.y); atomicAdd(gc+6,x1f.z); atomicAdd(gc+7,x1f.w);
    atomicAdd(gc+8,x2f.x); atomicAdd(gc+9,x2f.y); atomicAdd(gc+10,x2f.z); atomicAdd(gc+11,x2f.w);
    atomicAdd(gc+12,x3f.x); atomicAdd(gc+13,x3f.y); atomicAdd(gc+14,x3f.z); atomicAdd(gc+15,x3f.w);
    atomicAdd(gc+16,cf.x); atomicAdd(gc+17,cf.y); atomicAdd(gc+18,cf.z); atomicAdd(gc+19,cf.w);
}

// ---------------- per-graph offset Cg ----------------
__global__ void k_cg(const float* __restrict__ ke, const float* __restrict__ be) {
    int idx = blockIdx.x * 256 + threadIdx.x;            // BB*MHs = 262144
    if (idx >= BB*MHs) return;
    int b = idx >> 11;
    int mh = idx & 2047;
    int m = mh >> 5, h = mh & 31;
    float fac = g_fact[b];
    const float* k1 = ke + ((m*5 + 1)*HHs + h)*FINs;
    const float* k4 = ke + ((m*5 + 4)*HHs + h)*FINs;
    const float* gd = g_gd + b*FINs;
    const float* gc = g_gc + b*FINs;
    float s1 = 0.f, s4 = 0.f;
    #pragma unroll
    for (int f = 0; f < FINs; f++) { s1 += gd[f]*k1[f]; s4 += gc[f]*k4[f]; }
    g_Cg[idx] = be[mh] + fac*s1 + fac*fac*s4;
}

// ---------------- mma.sync GEMM + ReLU + per-graph reduction ----------------
// grid (16 mh-tiles, 391 node-tiles), 256 threads (8 warps, 4x2).
// D[128n x 128mh], K=64, bf16x3 split: Ahi*Whi + Ahi*Wlo + Alo*Whi.
__global__ __launch_bounds__(256, 2) void k_mm(const int* __restrict__ batch) {
    extern __shared__ char smem[];
    uint32_t sb = s2u(smem);
    int tid = threadIdx.x;
    int lane = tid & 31, warp = tid >> 5;
    int warpM = warp & 3, warpN = warp >> 2;
    int mb = blockIdx.x * 128, nb = blockIdx.y * 128;

    // ---- load 4 operand tiles into smem (row pitch 144B) ----
    {
        int r = tid >> 1, half = tid & 1;
        const uint4* Ah = (const uint4*)(g_Ahi + (size_t)(nb + r)*KKs + half*32);
        const uint4* Al = (const uint4*)(g_Alo + (size_t)(nb + r)*KKs + half*32);
        const uint4* Wh = (const uint4*)(g_Whi + (size_t)(mb + r)*KKs + half*32);
        const uint4* Wl = (const uint4*)(g_Wlo + (size_t)(mb + r)*KKs + half*32);
        char* base = smem + r*TPITCHB + half*64;
        #pragma unroll
        for (int i = 0; i < 4; i++) {
            *(uint4*)(base + SM_A_HI + i*16) = Ah[i];
            *(uint4*)(base + SM_A_LO + i*16) = Al[i];
            *(uint4*)(base + SM_W_HI + i*16) = Wh[i];
            *(uint4*)(base + SM_W_LO + i*16) = Wl[i];
        }
    }
    __syncthreads();

    float c[2][8][4];
    #pragma unroll
    for (int i = 0; i < 2; i++)
        #pragma unroll
        for (int j = 0; j < 8; j++)
            #pragma unroll
            for (int q = 0; q < 4; q++) c[i][j][q] = 0.f;

    // ldmatrix per-lane address components
    int g8 = lane >> 3, l7 = lane & 7;
    int arow = ((g8 & 1) << 3) + l7;           // 0..15
    int aoff = (g8 >> 1) << 4;                 // 0 / 16 bytes
    int brow = ((g8 >> 1) << 3) + l7;
    int boff = (g8 & 1) << 4;
    uint32_t aHi = sb + SM_A_HI + (warpM*32 + arow)*TPITCHB + aoff;
    uint32_t aLo = aHi + (SM_A_LO - SM_A_HI);
    uint32_t bHi = sb + SM_W_HI + (warpN*64 + brow)*TPITCHB + boff;
    uint32_t bLo = bHi + (SM_W_LO - SM_W_HI);

    #pragma unroll
    for (int k = 0; k < 4; k++) {
        int kb = k * 32;                       // 16 k-elems = 32 bytes
        uint32_t ah[2][4], al[2][4];
        #pragma unroll
        for (int i = 0; i < 2; i++) {
            LDM4(ah[i], aHi + i*16*TPITCHB + kb);
            LDM4(al[i], aLo + i*16*TPITCHB + kb);
        }
        #pragma unroll
        for (int jj = 0; jj < 4; jj++) {
            uint32_t bh[4], bl[4];
            LDM4(bh, bHi + jj*16*TPITCHB + kb);
            LDM4(bl, bLo + jj*16*TPITCHB + kb);
            #pragma unroll
            for (int i = 0; i < 2; i++) {
                mma16816(c[i][jj*2],   ah[i], bh[0], bh[1]);
                mma16816(c[i][jj*2+1], ah[i], bh[2], bh[3]);
                mma16816(c[i][jj*2],   ah[i], bl[0], bl[1]);
                mma16816(c[i][jj*2+1], ah[i], bl[2], bl[3]);
                mma16816(c[i][jj*2],   al[i], bh[0], bh[1]);
                mma16816(c[i][jj*2+1], al[i], bh[2], bh[3]);
            }
        }
    }
    __syncthreads();   // operand smem dead; reuse for epilogue

    // ---- epilogue: relu(C + Cg) -> buf, per-graph column sums ----
    int g0 = batch[nb];
    int nlast = nb + 127; if (nlast >= NN) nlast = NN - 1;
    int glast = batch[nlast];
    int*   flg = (int*)smem;                   // [128]
    float* cgs = (float*)(smem + 512);         // [2][128]
    float* buf = (float*)(smem + 2048);        // [128][BUFW]
    if (tid < 128) {
        int n = nb + tid;
        flg[tid] = (n < NN && batch[n] != g0) ? 1 : 0;
    } else {
        int t = tid - 128;
        cgs[t]       = g_Cg[(size_t)g0   *MHs + mb + t];
        cgs[128 + t] = g_Cg[(size_t)glast*MHs + mb + t];
    }
    __syncthreads();

    #pragma unroll
    for (int i = 0; i < 2; i++) {
        int ra = warpM*32 + i*16 + (lane >> 2);
        int rb = ra + 8;
        bool va = (nb + ra) < NN, vb = (nb + rb) < NN;
        const float* ca = cgs + flg[ra]*128;
        const float* cb = cgs + flg[rb]*128;
        #pragma unroll
        for (int j = 0; j < 8; j++) {
            int col = warpN*64 + j*8 + (lane & 3)*2;
            float2 v0, v1;
            v0.x = va ? fmaxf(c[i][j][0] + ca[col],   0.f) : 0.f;
            v0.y = va ? fmaxf(c[i][j][1] + ca[col+1], 0.f) : 0.f;
            v1.x = vb ? fmaxf(c[i][j][2] + cb[col],   0.f) : 0.f;
            v1.y = vb ? fmaxf(c[i][j][3] + cb[col+1], 0.f) : 0.f;
            *(float2*)(buf + (size_t)ra*BUFW + col) = v0;
            *(float2*)(buf + (size_t)rb*BUFW + col) = v1;
        }
    }
    __syncthreads();

    {
        int col = tid & 127, half = tid >> 7;
        float s0 = 0.f, s1 = 0.f;
        int r0 = half * 64;
        #pragma unroll 8
        for (int r = r0; r < r0 + 64; r++) {
            float v = buf[(size_t)r*BUFW + col];
            if (flg[r]) s1 += v; else s0 += v;
        }
        atomicAdd(&g_acc[(size_t)g0*MHs + mb + col], s0);
        if (glast != g0) atomicAdd(&g_acc[(size_t)glast*MHs + mb + col], s1);
    }
}

// ---------------- final ----------------
__global__ void k_final(const float* __restrict__ be, const float* __restrict__ kinv,
                        float* __restrict__ out) {
    int b = blockIdx.x;
    int m = threadIdx.x;
    float fac = g_fact[b];
    const float* acc = g_acc + (size_t)b*MHs + m*HHs;
    const float* beh = be + m*HHs;
    const float* kv  = kinv + m*HHs;
    float s = 0.f;
    #pragma unroll
    for (int h = 0; h < HHs; h++)
        s += (acc[h]*fac - fmaxf(beh[h], 0.f)) * kv[h];
    out[b*MMs + m] = s;
}

extern "C" void kernel_launch(void* const* d_in, const int* in_sizes, int n_in,
                              void* d_out, int out_size) {
    const float* x    = (const float*)d_in[0];
    const float* ea   = (const float*)d_in[1];
    const float* ke   = (const float*)d_in[2];
    const float* kinv = (const float*)d_in[3];
    const float* be   = (const float*)d_in[4];
    // d_in[5] = bias_inv: cancels in psi - zerograph
    const int* ei     = (const int*)d_in[6];
    const int* batch  = (const int*)d_in[7];
    float* out = (float*)d_out;

    cudaFuncSetAttribute(k_mm, cudaFuncAttributeMaxDynamicSharedMemorySize, SMEM_BYTES);

    k_init<<<1024, 256>>>();
    k_count<<<(NN+255)/256, 256>>>(batch);
    k_fact<<<1, BB>>>();
    k_wprep<<<(MHs*KKs)/256, 256>>>(ke);
    k_edge<<<(EE+255)/256, 256>>>(ei, ea);
    k_node<<<(NN+255)/256, 256>>>(x, ea, batch);
    k_cg<<<(BB*MHs)/256, 256>>>(ke, be);
    dim3 gg(MHs/128, NTILES);
    k_mm<<<gg, 256, SMEM_BYTES>>>(batch);
    k_final<<<BB, MMs>>>(be, kinv, out);
}

// round 6
// speedup vs baseline: 3.2736x; 1.8900x over previous
#include <cuda_runtime.h>
#include <cuda_bf16.h>
#include <cstdint>

// Problem constants (fixed by the reference)
#define NN   50000
#define EE   1600000
#define BB   128
#define FXs  16
#define FEs  4
#define FINs 20
#define MMs  64
#define HHs  32
#define MHs  2048   // M*H
#define KK2  48     // reduced K: x(16)|de(4)|x*fac(16,comb w)|rows*fac(4)|cols*fac(4)|0(4)
#define NTILES 391
#define NPAD (NTILES*128)  // 50048

// smem layout for k_mm (dynamic)
// phase 1 (operands): 4 tiles of 128 rows x 112B pitch (96B real = 48 bf16)
#define SM_A_HI 0
#define SM_A_LO 14336
#define SM_W_HI 28672
#define SM_W_LO 43008
#define TPITCHB 112
// phase 2 (epilogue, reuses same memory): flg@0 (512B), cgs@512 (1KB), buf@2048
#define BUFW 132
#define SMEM_BYTES 69632

// ---------------- scratch (device globals: no allocation allowed) ----------------
__device__ __align__(16) float g_rows[NN*FEs];
__device__ __align__(16) float g_cols[NN*FEs];
__device__ int   g_winner[NN];
__device__ int   g_cnt[BB];
__device__ float g_fact[BB];
__device__ __align__(16) float g_gd[BB*FINs];
__device__ __align__(16) float g_gc[BB*FINs];
__device__ __align__(16) __nv_bfloat16 g_Ahi[NPAD*KK2];
__device__ __align__(16) __nv_bfloat16 g_Alo[NPAD*KK2];
__device__ __align__(16) __nv_bfloat16 g_Whi[MHs*KK2];   // [mh][k], K-major
__device__ __align__(16) __nv_bfloat16 g_Wlo[MHs*KK2];
__device__ __align__(16) float g_Cg[BB*MHs];             // per-graph offset (+bias_equiv)
__device__ float g_acc[BB*MHs];                          // segsum(relu(...)) accumulator

__device__ __forceinline__ float4 f4s(float4 v, float s) {
    return make_float4(v.x*s, v.y*s, v.z*s, v.w*s);
}
__device__ __forceinline__ uint32_t pk2(__nv_bfloat16 a, __nv_bfloat16 b) {
    __nv_bfloat162 t = __halves2bfloat162(a, b);
    return *reinterpret_cast<uint32_t*>(&t);
}
__device__ __forceinline__ uint32_t s2u(const void* p) {
    uint32_t a;
    asm("{ .reg .u64 t; cvta.to.shared.u64 t, %1; cvt.u32.u64 %0, t; }" : "=r"(a) : "l"(p));
    return a;
}
__device__ __forceinline__ void red4(float* p, float4 v) {
    asm volatile("red.global.add.v4.f32 [%0], {%1, %2, %3, %4};"
                 :: "l"(p), "f"(v.x), "f"(v.y), "f"(v.z), "f"(v.w) : "memory");
}
#define LDM4(r, addr) \
    asm volatile("ldmatrix.sync.aligned.m8n8.x4.shared.b16 {%0,%1,%2,%3}, [%4];" \
        : "=r"((r)[0]), "=r"((r)[1]), "=r"((r)[2]), "=r"((r)[3]) : "r"(addr))

__device__ __forceinline__ void mma16816(float* c, const uint32_t* a,
                                         uint32_t b0, uint32_t b1) {
    asm volatile(
        "mma.sync.aligned.m16n8k16.row.col.f32.bf16.bf16.f32 "
        "{%0,%1,%2,%3}, {%4,%5,%6,%7}, {%8,%9}, {%0,%1,%2,%3};"
        : "+f"(c[0]), "+f"(c[1]), "+f"(c[2]), "+f"(c[3])
        : "r"(a[0]), "r"(a[1]), "r"(a[2]), "r"(a[3]), "r"(b0), "r"(b1));
}

// ---------------- init ----------------
__global__ void k_init() {
    int idx = blockIdx.x * 256 + threadIdx.x;           // grid covers 262144
    if (idx < NN*FEs) { g_rows[idx] = 0.f; g_cols[idx] = 0.f; }
    if (idx < NN)      g_winner[idx] = -1;
    if (idx < BB*MHs)  g_acc[idx] = 0.f;
    if (idx < BB*FINs) { g_gd[idx] = 0.f; g_gc[idx] = 0.f; }
    if (idx < BB)      g_cnt[idx] = 0;
    if (idx < (NPAD-NN)*KK2) {                          // zero A padding rows
        g_Ahi[NN*KK2 + idx] = __float2bfloat16(0.f);
        g_Alo[NN*KK2 + idx] = __float2bfloat16(0.f);
    }
}

// ---------------- per-graph node counts (smem histogram) ----------------
__global__ void k_count(const int* __restrict__ batch) {
    __shared__ int h[BB];
    int tid = threadIdx.x;
    if (tid < BB) h[tid] = 0;
    __syncthreads();
    int n = blockIdx.x * 256 + tid;
    if (n < NN) atomicAdd(&h[batch[n]], 1);
    __syncthreads();
    if (tid < BB && h[tid]) atomicAdd(&g_cnt[tid], h[tid]);
}
__global__ void k_fact() {
    int b = threadIdx.x;
    if (b < BB) g_fact[b] = 1.0f / (float)g_cnt[b];
}

// ---------------- weight prep: W[mh][k] bf16 hi/lo (K=48, combined x-block) ----------------
__global__ void k_wprep(const float* __restrict__ ke) {
    int idx = blockIdx.x * 256 + threadIdx.x;           // MHs*KK2 = 98304
    if (idx >= MHs*KK2) return;
    int mh = idx / KK2, k = idx % KK2;
    int m = mh >> 5, h = mh & 31;
    const float* kb = ke + (m*5*HHs + h)*FINs;          // stride between bsel: HHs*FINs
    const int BS = HHs*FINs;
    float v = 0.f;
    if (k < 20)       v = kb[k];                                  // diag
    else if (k < 36)  v = kb[2*BS + (k-20)] + kb[3*BS + (k-20)];  // combined x*fac
    else if (k < 40)  v = kb[2*BS + (k-20)];                      // rows attrs (f=16..19)
    else if (k < 44)  v = kb[3*BS + (k-24)];                      // cols attrs (f=16..19)
    __nv_bfloat16 hi = __float2bfloat16(v);
    g_Whi[idx] = hi;
    g_Wlo[idx] = __float2bfloat16(v - __bfloat162float(hi));
}

// ---------------- edge scatter (vectorized red) ----------------
__global__ void k_edge(const int* __restrict__ ei, const float* __restrict__ ea) {
    int e = blockIdx.x * 256 + threadIdx.x;
    if (e >= EE) return;
    int s = ei[e], d = ei[EE + e];
    float4 a = ((const float4*)ea)[e];
    red4(g_rows + s*4, a);
    red4(g_cols + d*4, a);
    if (s == d) atomicMax(&g_winner[s], e);
}

// ---------------- per-node basis build (bf16 hi/lo, K=48) + per-graph partial sums ----------
__global__ void k_node(const float* __restrict__ x, const float* __restrict__ ea,
                       const int* __restrict__ batch) {
    int n = blockIdx.x * 256 + threadIdx.x;
    if (n >= NN) return;
    int b = batch[n];
    float fac = g_fact[b];
    const float4* xr = (const float4*)(x + (size_t)n*FXs);
    float4 x0 = xr[0], x1 = xr[1], x2 = xr[2], x3 = xr[3];
    int w = g_winner[n];
    float4 de = make_float4(0.f,0.f,0.f,0.f);
    if (w >= 0) de = ((const float4*)ea)[w];
    float4 r = ((const float4*)g_rows)[n];
    float4 c = ((const float4*)g_cols)[n];
    float4 x0f = f4s(x0,fac), x1f = f4s(x1,fac), x2f = f4s(x2,fac), x3f = f4s(x3,fac);
    float4 rf = f4s(r,fac), cf = f4s(c,fac);

    uint32_t hib[24], lob[24];
    float4 vals[12] = { x0, x1, x2, x3, de,
                        x0f, x1f, x2f, x3f, rf, cf,
                        make_float4(0.f,0.f,0.f,0.f) };
    #pragma unroll
    for (int i = 0; i < 12; i++) {
        float4 v = vals[i];
        __nv_bfloat16 ax = __float2bfloat16(v.x), ay = __float2bfloat16(v.y);
        __nv_bfloat16 az = __float2bfloat16(v.z), aw = __float2bfloat16(v.w);
        hib[2*i]   = pk2(ax, ay);
        hib[2*i+1] = pk2(az, aw);
        lob[2*i]   = pk2(__float2bfloat16(v.x - __bfloat162float(ax)),
                         __float2bfloat16(v.y - __bfloat162float(ay)));
        lob[2*i+1] = pk2(__float2bfloat16(v.z - __bfloat162float(az)),
                         __float2bfloat16(v.w - __bfloat162float(aw)));
    }
    uint4* dh = (uint4*)(g_Ahi + (size_t)n*KK2);
    uint4* dl = (uint4*)(g_Alo + (size_t)n*KK2);
    #pragma unroll
    for (int i = 0; i < 6; i++) { dh[i] = ((uint4*)hib)[i]; dl[i] = ((uint4*)lob)[i]; }

    float* gd = g_gd + b*FINs;
    red4(gd+0,  x0); red4(gd+4,  x1); red4(gd+8,  x2); red4(gd+12, x3); red4(gd+16, de);
    float* gc = g_gc + b*FINs;
    red4(gc+0, x0f); red4(gc+4, x1f); red4(gc+8, x2f); red4(gc+12, x3f); red4(gc+16, cf);
}

// ---------------- per-graph offset Cg ----------------
__global__ void k_cg(const float* __restrict__ ke, const float* __restrict__ be) {
    int idx = blockIdx.x * 256 + threadIdx.x;            // BB*MHs = 262144
    if (idx >= BB*MHs) return;
    int b = idx >> 11;
    int mh = idx & 2047;
    int m = mh >> 5, h = mh & 31;
    float fac = g_fact[b];
    const float* k1 = ke + ((m*5 + 1)*HHs + h)*FINs;
    const float* k4 = ke + ((m*5 + 4)*HHs + h)*FINs;
    const float* gd = g_gd + b*FINs;
    const float* gc = g_gc + b*FINs;
    float s1 = 0.f, s4 = 0.f;
    #pragma unroll
    for (int f = 0; f < FINs; f++) { s1 += gd[f]*k1[f]; s4 += gc[f]*k4[f]; }
    g_Cg[idx] = be[mh] + fac*s1 + fac*fac*s4;
}

// ---------------- mma.sync GEMM + ReLU + per-graph reduction ----------------
// grid (16 mh-tiles, 391 node-tiles), 256 threads (8 warps, 4x2).
// D[128n x 128mh], K=48, bf16x3 split: Ahi*Whi + Ahi*Wlo + Alo*Whi.
__global__ __launch_bounds__(256, 2) void k_mm(const int* __restrict__ batch) {
    extern __shared__ char smem[];
    uint32_t sb = s2u(smem);
    int tid = threadIdx.x;
    int lane = tid & 31, warp = tid >> 5;
    int warpM = warp & 3, warpN = warp >> 2;
    int mb = blockIdx.x * 128, nb = blockIdx.y * 128;

    // ---- load 4 operand tiles into smem (row pitch 112B, 96B real) ----
    {
        int r = tid >> 1, half = tid & 1;
        const uint4* Ah = (const uint4*)(g_Ahi + (size_t)(nb + r)*KK2) + half*3;
        const uint4* Al = (const uint4*)(g_Alo + (size_t)(nb + r)*KK2) + half*3;
        const uint4* Wh = (const uint4*)(g_Whi + (size_t)(mb + r)*KK2) + half*3;
        const uint4* Wl = (const uint4*)(g_Wlo + (size_t)(mb + r)*KK2) + half*3;
        char* base = smem + r*TPITCHB + half*48;
        #pragma unroll
        for (int i = 0; i < 3; i++) {
            *(uint4*)(base + SM_A_HI + i*16) = Ah[i];
            *(uint4*)(base + SM_A_LO + i*16) = Al[i];
            *(uint4*)(base + SM_W_HI + i*16) = Wh[i];
            *(uint4*)(base + SM_W_LO + i*16) = Wl[i];
        }
    }
    __syncthreads();

    float c[2][8][4];
    #pragma unroll
    for (int i = 0; i < 2; i++)
        #pragma unroll
        for (int j = 0; j < 8; j++)
            #pragma unroll
            for (int q = 0; q < 4; q++) c[i][j][q] = 0.f;

    // ldmatrix per-lane address components
    int g8 = lane >> 3, l7 = lane & 7;
    int arow = ((g8 & 1) << 3) + l7;           // 0..15
    int aoff = (g8 >> 1) << 4;                 // 0 / 16 bytes
    int brow = ((g8 >> 1) << 3) + l7;
    int boff = (g8 & 1) << 4;
    uint32_t aHi = sb + SM_A_HI + (warpM*32 + arow)*TPITCHB + aoff;
    uint32_t aLo = aHi + (SM_A_LO - SM_A_HI);
    uint32_t bHi = sb + SM_W_HI + (warpN*64 + brow)*TPITCHB + boff;
    uint32_t bLo = bHi + (SM_W_LO - SM_W_HI);

    #pragma unroll
    for (int k = 0; k < 3; k++) {
        int kb = k * 32;                       // 16 k-elems = 32 bytes
        uint32_t ah[2][4], al[2][4];
        #pragma unroll
        for (int i = 0; i < 2; i++) {
            LDM4(ah[i], aHi + i*16*TPITCHB + kb);
            LDM4(al[i], aLo + i*16*TPITCHB + kb);
        }
        #pragma unroll
        for (int jj = 0; jj < 4; jj++) {
            uint32_t bh[4], bl[4];
            LDM4(bh, bHi + jj*16*TPITCHB + kb);
            LDM4(bl, bLo + jj*16*TPITCHB + kb);
            #pragma unroll
            for (int i = 0; i < 2; i++) {
                mma16816(c[i][jj*2],   ah[i], bh[0], bh[1]);
                mma16816(c[i][jj*2+1], ah[i], bh[2], bh[3]);
                mma16816(c[i][jj*2],   ah[i], bl[0], bl[1]);
                mma16816(c[i][jj*2+1], ah[i], bl[2], bl[3]);
                mma16816(c[i][jj*2],   al[i], bh[0], bh[1]);
                mma16816(c[i][jj*2+1], al[i], bh[2], bh[3]);
            }
        }
    }
    __syncthreads();   // operand smem dead; reuse for epilogue

    // ---- epilogue: relu(C + Cg) -> buf, per-graph column sums ----
    int g0 = batch[nb];
    int nlast = nb + 127; if (nlast >= NN) nlast = NN - 1;
    int glast = batch[nlast];
    int*   flg = (int*)smem;                   // [128]
    float* cgs = (float*)(smem + 512);         // [2][128]
    float* buf = (float*)(smem + 2048);        // [128][BUFW]
    if (tid < 128) {
        int n = nb + tid;
        flg[tid] = (n < NN && batch[n] != g0) ? 1 : 0;
    } else {
        int t = tid - 128;
        cgs[t]       = g_Cg[(size_t)g0   *MHs + mb + t];
        cgs[128 + t] = g_Cg[(size_t)glast*MHs + mb + t];
    }
    __syncthreads();

    #pragma unroll
    for (int i = 0; i < 2; i++) {
        int ra = warpM*32 + i*16 + (lane >> 2);
        int rb = ra + 8;
        bool va = (nb + ra) < NN, vb = (nb + rb) < NN;
        const float* ca = cgs + flg[ra]*128;
        const float* cb = cgs + flg[rb]*128;
        #pragma unroll
        for (int j = 0; j < 8; j++) {
            int col = warpN*64 + j*8 + (lane & 3)*2;
            float2 v0, v1;
            v0.x = va ? fmaxf(c[i][j][0] + ca[col],   0.f) : 0.f;
            v0.y = va ? fmaxf(c[i][j][1] + ca[col+1], 0.f) : 0.f;
            v1.x = vb ? fmaxf(c[i][j][2] + cb[col],   0.f) : 0.f;
            v1.y = vb ? fmaxf(c[i][j][3] + cb[col+1], 0.f) : 0.f;
            *(float2*)(buf + (size_t)ra*BUFW + col) = v0;
            *(float2*)(buf + (size_t)rb*BUFW + col) = v1;
        }
    }
    __syncthreads();

    {
        int col = tid & 127, half = tid >> 7;
        float s0 = 0.f, s1 = 0.f;
        int r0 = half * 64;
        #pragma unroll 8
        for (int r = r0; r < r0 + 64; r++) {
            float v = buf[(size_t)r*BUFW + col];
            if (flg[r]) s1 += v; else s0 += v;
        }
        atomicAdd(&g_acc[(size_t)g0*MHs + mb + col], s0);
        if (glast != g0) atomicAdd(&g_acc[(size_t)glast*MHs + mb + col], s1);
    }
}

// ---------------- final ----------------
__global__ void k_final(const float* __restrict__ be, const float* __restrict__ kinv,
                        float* __restrict__ out) {
    int b = blockIdx.x;
    int m = threadIdx.x;
    float fac = g_fact[b];
    const float* acc = g_acc + (size_t)b*MHs + m*HHs;
    const float* beh = be + m*HHs;
    const float* kv  = kinv + m*HHs;
    float s = 0.f;
    #pragma unroll
    for (int h = 0; h < HHs; h++)
        s += (acc[h]*fac - fmaxf(beh[h], 0.f)) * kv[h];
    out[b*MMs + m] = s;
}

extern "C" void kernel_launch(void* const* d_in, const int* in_sizes, int n_in,
                              void* d_out, int out_size) {
    const float* x    = (const float*)d_in[0];
    const float* ea   = (const float*)d_in[1];
    const float* ke   = (const float*)d_in[2];
    const float* kinv = (const float*)d_in[3];
    const float* be   = (const float*)d_in[4];
    // d_in[5] = bias_inv: cancels in psi - zerograph
    const int* ei     = (const int*)d_in[6];
    const int* batch  = (const int*)d_in[7];
    float* out = (float*)d_out;

    cudaFuncSetAttribute(k_mm, cudaFuncAttributeMaxDynamicSharedMemorySize, SMEM_BYTES);

    k_init<<<1024, 256>>>();
    k_count<<<(NN+255)/256, 256>>>(batch);
    k_fact<<<1, BB>>>();
    k_wprep<<<(MHs*KK2+255)/256, 256>>>(ke);
    k_edge<<<(EE+255)/256, 256>>>(ei, ea);
    k_node<<<(NN+255)/256, 256>>>(x, ea, batch);
    k_cg<<<(BB*MHs)/256, 256>>>(ke, be);
    dim3 gg(MHs/128, NTILES);
    k_mm<<<gg, 256, SMEM_BYTES>>>(batch);
    k_final<<<BB, MMs>>>(be, kinv, out);
}

// round 7
// speedup vs baseline: 3.6367x; 1.1109x over previous
#include <cuda_runtime.h>
#include <cuda_fp16.h>
#include <cstdint>

// Problem constants (fixed by the reference)
#define NN   50000
#define EE   1600000
#define BB   128
#define FXs  16
#define FEs  4
#define FINs 20
#define MMs  64
#define HHs  32
#define MHs  2048   // M*H
#define KK2  48     // reduced K: x(16)|de(4)|x*fac(16,comb w)|rows*fac(4)|cols*fac(4)|0(4)
#define NTILES 391
#define NPAD (NTILES*128)  // 50048

// smem layout for k_mm (dynamic)
// phase 1 (operands): 3 tiles of 128 rows x 112B pitch (96B real = 48 fp16)
#define SM_A  0
#define SM_WH 14336
#define SM_WL 28672
#define TPITCHB 112
// phase 2 (epilogue, reuses same memory): flg@0 (512B), cgs@512 (1KB), buf@2048
#define BUFW 132
#define SMEM_BYTES 69632

// ---------------- scratch (device globals: no allocation allowed) ----------------
__device__ __align__(16) float g_rows[NN*FEs];
__device__ __align__(16) float g_cols[NN*FEs];
__device__ int   g_winner[NN];
__device__ int   g_cnt[BB];
__device__ float g_fact[BB];
__device__ __align__(16) float g_gd[BB*FINs];
__device__ __align__(16) float g_gc[BB*FINs];
__device__ __align__(16) __half g_A16[NPAD*KK2];
__device__ __align__(16) __half g_Whi[MHs*KK2];   // [mh][k], K-major
__device__ __align__(16) __half g_Wlo[MHs*KK2];
__device__ __align__(16) float g_Cg[BB*MHs];      // per-graph offset (+bias_equiv)
__device__ float g_acc[BB*MHs];                   // segsum(relu(...)) accumulator

__device__ __forceinline__ float4 f4s(float4 v, float s) {
    return make_float4(v.x*s, v.y*s, v.z*s, v.w*s);
}
__device__ __forceinline__ uint32_t pkh2(float a, float b) {
    __half2 t = __floats2half2_rn(a, b);
    return *reinterpret_cast<uint32_t*>(&t);
}
__device__ __forceinline__ uint32_t s2u(const void* p) {
    uint32_t a;
    asm("{ .reg .u64 t; cvta.to.shared.u64 t, %1; cvt.u32.u64 %0, t; }" : "=r"(a) : "l"(p));
    return a;
}
__device__ __forceinline__ void red4(float* p, float4 v) {
    asm volatile("red.global.add.v4.f32 [%0], {%1, %2, %3, %4};"
                 :: "l"(p), "f"(v.x), "f"(v.y), "f"(v.z), "f"(v.w) : "memory");
}
#define LDM4(r, addr) \
    asm volatile("ldmatrix.sync.aligned.m8n8.x4.shared.b16 {%0,%1,%2,%3}, [%4];" \
        : "=r"((r)[0]), "=r"((r)[1]), "=r"((r)[2]), "=r"((r)[3]) : "r"(addr))

__device__ __forceinline__ void mma16816(float* c, const uint32_t* a,
                                         uint32_t b0, uint32_t b1) {
    asm volatile(
        "mma.sync.aligned.m16n8k16.row.col.f32.f16.f16.f32 "
        "{%0,%1,%2,%3}, {%4,%5,%6,%7}, {%8,%9}, {%0,%1,%2,%3};"
        : "+f"(c[0]), "+f"(c[1]), "+f"(c[2]), "+f"(c[3])
        : "r"(a[0]), "r"(a[1]), "r"(a[2]), "r"(a[3]), "r"(b0), "r"(b1));
}

// ---------------- init ----------------
__global__ void k_init() {
    int idx = blockIdx.x * 256 + threadIdx.x;           // grid covers 262144
    if (idx < NN*FEs) { g_rows[idx] = 0.f; g_cols[idx] = 0.f; }
    if (idx < NN)      g_winner[idx] = -1;
    if (idx < BB*FINs) { g_gd[idx] = 0.f; g_gc[idx] = 0.f; }
    if (idx < BB)      g_cnt[idx] = 0;
    if (idx < (NPAD-NN)*KK2)                            // zero A padding rows
        g_A16[NN*KK2 + idx] = __float2half(0.f);
}

// ---------------- per-graph node counts (smem histogram) ----------------
__global__ void k_count(const int* __restrict__ batch) {
    __shared__ int h[BB];
    int tid = threadIdx.x;
    if (tid < BB) h[tid] = 0;
    __syncthreads();
    int n = blockIdx.x * 256 + tid;
    if (n < NN) atomicAdd(&h[batch[n]], 1);
    __syncthreads();
    if (tid < BB && h[tid]) atomicAdd(&g_cnt[tid], h[tid]);
}
__global__ void k_fact() {
    int b = threadIdx.x;
    if (b < BB) g_fact[b] = 1.0f / (float)g_cnt[b];
}

// ---------------- weight prep: W[mh][k] fp16 hi/lo (K=48, combined x-block) ----------------
__global__ void k_wprep(const float* __restrict__ ke) {
    int idx = blockIdx.x * 256 + threadIdx.x;           // MHs*KK2 = 98304
    if (idx >= MHs*KK2) return;
    int mh = idx / KK2, k = idx % KK2;
    int m = mh >> 5, h = mh & 31;
    const float* kb = ke + (m*5*HHs + h)*FINs;          // stride between bsel: HHs*FINs
    const int BS = HHs*FINs;
    float v = 0.f;
    if (k < 20)       v = kb[k];                                  // diag
    else if (k < 36)  v = kb[2*BS + (k-20)] + kb[3*BS + (k-20)];  // combined x*fac
    else if (k < 40)  v = kb[2*BS + (k-20)];                      // rows attrs (f=16..19)
    else if (k < 44)  v = kb[3*BS + (k-24)];                      // cols attrs (f=16..19)
    __half hi = __float2half_rn(v);
    g_Whi[idx] = hi;
    g_Wlo[idx] = __float2half_rn(v - __half2float(hi));
}

// ---------------- edge scatter (vectorized red) ----------------
__global__ void k_edge(const int* __restrict__ ei, const float* __restrict__ ea) {
    int e = blockIdx.x * 256 + threadIdx.x;
    if (e >= EE) return;
    int s = ei[e], d = ei[EE + e];
    float4 a = ((const float4*)ea)[e];
    red4(g_rows + s*4, a);
    red4(g_cols + d*4, a);
    if (s == d) atomicMax(&g_winner[s], e);
}

// ---------------- per-node basis build (fp16, K=48) + per-graph partial sums ----------
__global__ void k_node(const float* __restrict__ x, const float* __restrict__ ea,
                       const int* __restrict__ batch) {
    int n = blockIdx.x * 256 + threadIdx.x;
    if (n >= NN) return;
    int b = batch[n];
    float fac = g_fact[b];
    const float4* xr = (const float4*)(x + (size_t)n*FXs);
    float4 x0 = xr[0], x1 = xr[1], x2 = xr[2], x3 = xr[3];
    int w = g_winner[n];
    float4 de = make_float4(0.f,0.f,0.f,0.f);
    if (w >= 0) de = ((const float4*)ea)[w];
    float4 r = ((const float4*)g_rows)[n];
    float4 c = ((const float4*)g_cols)[n];
    float4 x0f = f4s(x0,fac), x1f = f4s(x1,fac), x2f = f4s(x2,fac), x3f = f4s(x3,fac);
    float4 rf = f4s(r,fac), cf = f4s(c,fac);

    uint32_t hb[24];
    float4 vals[12] = { x0, x1, x2, x3, de,
                        x0f, x1f, x2f, x3f, rf, cf,
                        make_float4(0.f,0.f,0.f,0.f) };
    #pragma unroll
    for (int i = 0; i < 12; i++) {
        float4 v = vals[i];
        hb[2*i]   = pkh2(v.x, v.y);
        hb[2*i+1] = pkh2(v.z, v.w);
    }
    uint4* dh = (uint4*)(g_A16 + (size_t)n*KK2);
    #pragma unroll
    for (int i = 0; i < 6; i++) dh[i] = ((uint4*)hb)[i];

    float* gd = g_gd + b*FINs;
    red4(gd+0,  x0); red4(gd+4,  x1); red4(gd+8,  x2); red4(gd+12, x3); red4(gd+16, de);
    float* gc = g_gc + b*FINs;
    red4(gc+0, x0f); red4(gc+4, x1f); red4(gc+8, x2f); red4(gc+12, x3f); red4(gc+16, cf);
}

// ---------------- per-graph offset Cg (+ zero g_acc) ----------------
__global__ void k_cg(const float* __restrict__ ke, const float* __restrict__ be) {
    int idx = blockIdx.x * 256 + threadIdx.x;            // BB*MHs = 262144
    if (idx >= BB*MHs) return;
    g_acc[idx] = 0.f;
    int b = idx >> 11;
    int mh = idx & 2047;
    int m = mh >> 5, h = mh & 31;
    float fac = g_fact[b];
    const float* k1 = ke + ((m*5 + 1)*HHs + h)*FINs;
    const float* k4 = ke + ((m*5 + 4)*HHs + h)*FINs;
    const float* gd = g_gd + b*FINs;
    const float* gc = g_gc + b*FINs;
    float s1 = 0.f, s4 = 0.f;
    #pragma unroll
    for (int f = 0; f < FINs; f++) { s1 += gd[f]*k1[f]; s4 += gc[f]*k4[f]; }
    g_Cg[idx] = be[mh] + fac*s1 + fac*fac*s4;
}

// ---------------- mma.sync GEMM + ReLU + per-graph reduction ----------------
// grid (16 mh-tiles, 391 node-tiles), 256 threads (8 warps, 4x2).
// D[128n x 128mh], K=48, fp16 2-term split: A16*Whi + A16*Wlo.
__global__ __launch_bounds__(256, 2) void k_mm(const int* __restrict__ batch) {
    extern __shared__ char smem[];
    uint32_t sb = s2u(smem);
    int tid = threadIdx.x;
    int lane = tid & 31, warp = tid >> 5;
    int warpM = warp & 3, warpN = warp >> 2;
    int mb = blockIdx.x * 128, nb = blockIdx.y * 128;

    // ---- load 3 operand tiles into smem (row pitch 112B, 96B real) ----
    {
        int r = tid >> 1, half = tid & 1;
        const uint4* Ah = (const uint4*)(g_A16 + (size_t)(nb + r)*KK2) + half*3;
        const uint4* Wh = (const uint4*)(g_Whi + (size_t)(mb + r)*KK2) + half*3;
        const uint4* Wl = (const uint4*)(g_Wlo + (size_t)(mb + r)*KK2) + half*3;
        char* base = smem + r*TPITCHB + half*48;
        #pragma unroll
        for (int i = 0; i < 3; i++) {
            *(uint4*)(base + SM_A  + i*16) = Ah[i];
            *(uint4*)(base + SM_WH + i*16) = Wh[i];
            *(uint4*)(base + SM_WL + i*16) = Wl[i];
        }
    }
    __syncthreads();

    float c[2][8][4];
    #pragma unroll
    for (int i = 0; i < 2; i++)
        #pragma unroll
        for (int j = 0; j < 8; j++)
            #pragma unroll
            for (int q = 0; q < 4; q++) c[i][j][q] = 0.f;

    // ldmatrix per-lane address components
    int g8 = lane >> 3, l7 = lane & 7;
    int arow = ((g8 & 1) << 3) + l7;           // 0..15
    int aoff = (g8 >> 1) << 4;                 // 0 / 16 bytes
    int brow = ((g8 >> 1) << 3) + l7;
    int boff = (g8 & 1) << 4;
    uint32_t aA = sb + SM_A  + (warpM*32 + arow)*TPITCHB + aoff;
    uint32_t bH = sb + SM_WH + (warpN*64 + brow)*TPITCHB + boff;
    uint32_t bL = bH + (SM_WL - SM_WH);

    #pragma unroll
    for (int k = 0; k < 3; k++) {
        int kb = k * 32;                       // 16 k-elems = 32 bytes
        uint32_t a[2][4];
        #pragma unroll
        for (int i = 0; i < 2; i++)
            LDM4(a[i], aA + i*16*TPITCHB + kb);
        #pragma unroll
        for (int jj = 0; jj < 4; jj++) {
            uint32_t bh[4], bl[4];
            LDM4(bh, bH + jj*16*TPITCHB + kb);
            LDM4(bl, bL + jj*16*TPITCHB + kb);
            #pragma unroll
            for (int i = 0; i < 2; i++) {
                mma16816(c[i][jj*2],   a[i], bh[0], bh[1]);
                mma16816(c[i][jj*2+1], a[i], bh[2], bh[3]);
                mma16816(c[i][jj*2],   a[i], bl[0], bl[1]);
                mma16816(c[i][jj*2+1], a[i], bl[2], bl[3]);
            }
        }
    }
    __syncthreads();   // operand smem dead; reuse for epilogue

    // ---- epilogue: relu(C + Cg) -> buf, per-graph column sums ----
    int g0 = batch[nb];
    int nlast = nb + 127; if (nlast >= NN) nlast = NN - 1;
    int glast = batch[nlast];
    int*   flg = (int*)smem;                   // [128]
    float* cgs = (float*)(smem + 512);         // [2][128]
    float* buf = (float*)(smem + 2048);        // [128][BUFW]
    if (tid < 128) {
        int n = nb + tid;
        flg[tid] = (n < NN && batch[n] != g0) ? 1 : 0;
    } else {
        int t = tid - 128;
        cgs[t]       = g_Cg[(size_t)g0   *MHs + mb + t];
        cgs[128 + t] = g_Cg[(size_t)glast*MHs + mb + t];
    }
    __syncthreads();

    #pragma unroll
    for (int i = 0; i < 2; i++) {
        int ra = warpM*32 + i*16 + (lane >> 2);
        int rb = ra + 8;
        bool va = (nb + ra) < NN, vb = (nb + rb) < NN;
        const float* ca = cgs + flg[ra]*128;
        const float* cb = cgs + flg[rb]*128;
        #pragma unroll
        for (int j = 0; j < 8; j++) {
            int col = warpN*64 + j*8 + (lane & 3)*2;
            float2 v0, v1;
            v0.x = va ? fmaxf(c[i][j][0] + ca[col],   0.f) : 0.f;
            v0.y = va ? fmaxf(c[i][j][1] + ca[col+1], 0.f) : 0.f;
            v1.x = vb ? fmaxf(c[i][j][2] + cb[col],   0.f) : 0.f;
            v1.y = vb ? fmaxf(c[i][j][3] + cb[col+1], 0.f) : 0.f;
            *(float2*)(buf + (size_t)ra*BUFW + col) = v0;
            *(float2*)(buf + (size_t)rb*BUFW + col) = v1;
        }
    }
    __syncthreads();

    {
        int col = tid & 127, half = tid >> 7;
        float s0 = 0.f, s1 = 0.f;
        int r0 = half * 64;
        #pragma unroll 8
        for (int r = r0; r < r0 + 64; r++) {
            float v = buf[(size_t)r*BUFW + col];
            if (flg[r]) s1 += v; else s0 += v;
        }
        atomicAdd(&g_acc[(size_t)g0*MHs + mb + col], s0);
        if (glast != g0) atomicAdd(&g_acc[(size_t)glast*MHs + mb + col], s1);
    }
}

// ---------------- final ----------------
__global__ void k_final(const float* __restrict__ be, const float* __restrict__ kinv,
                        float* __restrict__ out) {
    int b = blockIdx.x;
    int m = threadIdx.x;
    float fac = g_fact[b];
    const float* acc = g_acc + (size_t)b*MHs + m*HHs;
    const float* beh = be + m*HHs;
    const float* kv  = kinv + m*HHs;
    float s = 0.f;
    #pragma unroll
    for (int h = 0; h < HHs; h++)
        s += (acc[h]*fac - fmaxf(beh[h], 0.f)) * kv[h];
    out[b*MMs + m] = s;
}

extern "C" void kernel_launch(void* const* d_in, const int* in_sizes, int n_in,
                              void* d_out, int out_size) {
    const float* x    = (const float*)d_in[0];
    const float* ea   = (const float*)d_in[1];
    const float* ke   = (const float*)d_in[2];
    const float* kinv = (const float*)d_in[3];
    const float* be   = (const float*)d_in[4];
    // d_in[5] = bias_inv: cancels in psi - zerograph
    const int* ei     = (const int*)d_in[6];
    const int* batch  = (const int*)d_in[7];
    float* out = (float*)d_out;

    cudaFuncSetAttribute(k_mm, cudaFuncAttributeMaxDynamicSharedMemorySize, SMEM_BYTES);

    k_init<<<1024, 256>>>();
    k_count<<<(NN+255)/256, 256>>>(batch);
    k_fact<<<1, BB>>>();
    k_wprep<<<(MHs*KK2+255)/256, 256>>>(ke);
    k_edge<<<(EE+255)/256, 256>>>(ei, ea);
    k_node<<<(NN+255)/256, 256>>>(x, ea, batch);
    k_cg<<<(BB*MHs)/256, 256>>>(ke, be);
    dim3 gg(MHs/128, NTILES);
    k_mm<<<gg, 256, SMEM_BYTES>>>(batch);
    k_final<<<BB, MMs>>>(be, kinv, out);
}

// round 8
// speedup vs baseline: 4.0283x; 1.1077x over previous
#include <cuda_runtime.h>
#include <cuda_fp16.h>
#include <cstdint>

// Problem constants (fixed by the reference)
#define NN   50000
#define EE   1600000
#define BB   128
#define FXs  16
#define FEs  4
#define FINs 20
#define MMs  64
#define HHs  32
#define MHs  2048   // M*H
#define KK2  48     // reduced K: x(16)|de(4)|x*fac(16,comb w)|rows*fac(4)|cols*fac(4)|0(4)
#define NTILES 391
#define NPAD (NTILES*128)  // 50048

// smem layout for k_mm (dynamic)
// phase 1 (operands): 2 tiles of 128 rows x 112B pitch (96B real = 48 fp16)
#define SM_A  0
#define SM_W  14336
#define TPITCHB 112
// phase 2 (epilogue, reuses same memory): flg@0 (512B), cgs@512 (1KB), buf@2048
#define BUFW 132
#define SMEM_BYTES 69632

// ---------------- scratch (device globals: no allocation allowed) ----------------
__device__ __align__(16) float g_rows[NN*FEs];
__device__ __align__(16) float g_cols[NN*FEs];
__device__ int   g_winner[NN];
__device__ float g_fact[BB];
__device__ __align__(16) float g_gd[BB*FINs];
__device__ __align__(16) float g_gc[BB*FINs];
__device__ __align__(16) __half g_A16[NPAD*KK2];
__device__ __align__(16) __half g_W16[MHs*KK2];   // [mh][k], K-major
__device__ __align__(16) float g_Cg[BB*MHs];      // per-graph offset (+bias_equiv)
__device__ float g_acc[BB*MHs];                   // segsum(relu(...)) accumulator

__device__ __forceinline__ float4 f4s(float4 v, float s) {
    return make_float4(v.x*s, v.y*s, v.z*s, v.w*s);
}
__device__ __forceinline__ uint32_t pkh2(float a, float b) {
    __half2 t = __floats2half2_rn(a, b);
    return *reinterpret_cast<uint32_t*>(&t);
}
__device__ __forceinline__ uint32_t s2u(const void* p) {
    uint32_t a;
    asm("{ .reg .u64 t; cvta.to.shared.u64 t, %1; cvt.u32.u64 %0, t; }" : "=r"(a) : "l"(p));
    return a;
}
__device__ __forceinline__ void red4(float* p, float4 v) {
    asm volatile("red.global.add.v4.f32 [%0], {%1, %2, %3, %4};"
                 :: "l"(p), "f"(v.x), "f"(v.y), "f"(v.z), "f"(v.w) : "memory");
}
#define LDM4(r, addr) \
    asm volatile("ldmatrix.sync.aligned.m8n8.x4.shared.b16 {%0,%1,%2,%3}, [%4];" \
        : "=r"((r)[0]), "=r"((r)[1]), "=r"((r)[2]), "=r"((r)[3]) : "r"(addr))

__device__ __forceinline__ void mma16816(float* c, const uint32_t* a,
                                         uint32_t b0, uint32_t b1) {
    asm volatile(
        "mma.sync.aligned.m16n8k16.row.col.f32.f16.f16.f32 "
        "{%0,%1,%2,%3}, {%4,%5,%6,%7}, {%8,%9}, {%0,%1,%2,%3};"
        : "+f"(c[0]), "+f"(c[1]), "+f"(c[2]), "+f"(c[3])
        : "r"(a[0]), "r"(a[1]), "r"(a[2]), "r"(a[3]), "r"(b0), "r"(b1));
}

// ---------------- init + weight prep (fused) ----------------
__global__ void k_init(const float* __restrict__ ke) {
    int idx = blockIdx.x * 256 + threadIdx.x;           // grid covers 262144
    if (idx < NN*FEs) { g_rows[idx] = 0.f; g_cols[idx] = 0.f; }
    if (idx < NN)      g_winner[idx] = -1;
    if (idx < BB*FINs) { g_gd[idx] = 0.f; g_gc[idx] = 0.f; }
    if (idx < (NPAD-NN)*KK2)                            // zero A padding rows
        g_A16[NN*KK2 + idx] = __float2half(0.f);
    if (idx < MHs*KK2) {                                // weight prep, single fp16
        int mh = idx / KK2, k = idx % KK2;
        int m = mh >> 5, h = mh & 31;
        const float* kb = ke + (m*5*HHs + h)*FINs;
        const int BS = HHs*FINs;
        float v = 0.f;
        if (k < 20)       v = kb[k];                                  // diag
        else if (k < 36)  v = kb[2*BS + (k-20)] + kb[3*BS + (k-20)];  // combined x*fac
        else if (k < 40)  v = kb[2*BS + (k-20)];                      // rows attrs
        else if (k < 44)  v = kb[3*BS + (k-24)];                      // cols attrs
        g_W16[idx] = __float2half_rn(v);
    }
}

// ---------------- per-graph node counts -> fact (single block) ----------------
__global__ void k_countfact(const int* __restrict__ batch) {
    __shared__ int h[BB];
    int tid = threadIdx.x;                              // 1024 threads
    if (tid < BB) h[tid] = 0;
    __syncthreads();
    for (int n = tid; n < NN; n += 1024) atomicAdd(&h[batch[n]], 1);
    __syncthreads();
    if (tid < BB) g_fact[tid] = 1.0f / (float)h[tid];
}

// ---------------- edge scatter (vectorized red) ----------------
__global__ void k_edge(const int* __restrict__ ei, const float* __restrict__ ea) {
    int e = blockIdx.x * 256 + threadIdx.x;
    if (e >= EE) return;
    int s = ei[e], d = ei[EE + e];
    float4 a = ((const float4*)ea)[e];
    red4(g_rows + s*4, a);
    red4(g_cols + d*4, a);
    if (s == d) atomicMax(&g_winner[s], e);
}

// ---------------- per-node basis build (fp16, K=48) + per-graph partial sums ----------
__global__ void k_node(const float* __restrict__ x, const float* __restrict__ ea,
                       const int* __restrict__ batch) {
    int n = blockIdx.x * 256 + threadIdx.x;
    if (n >= NN) return;
    int b = batch[n];
    float fac = g_fact[b];
    const float4* xr = (const float4*)(x + (size_t)n*FXs);
    float4 x0 = xr[0], x1 = xr[1], x2 = xr[2], x3 = xr[3];
    int w = g_winner[n];
    float4 de = make_float4(0.f,0.f,0.f,0.f);
    if (w >= 0) de = ((const float4*)ea)[w];
    float4 r = ((const float4*)g_rows)[n];
    float4 c = ((const float4*)g_cols)[n];
    float4 x0f = f4s(x0,fac), x1f = f4s(x1,fac), x2f = f4s(x2,fac), x3f = f4s(x3,fac);
    float4 rf = f4s(r,fac), cf = f4s(c,fac);

    uint32_t hb[24];
    float4 vals[12] = { x0, x1, x2, x3, de,
                        x0f, x1f, x2f, x3f, rf, cf,
                        make_float4(0.f,0.f,0.f,0.f) };
    #pragma unroll
    for (int i = 0; i < 12; i++) {
        float4 v = vals[i];
        hb[2*i]   = pkh2(v.x, v.y);
        hb[2*i+1] = pkh2(v.z, v.w);
    }
    uint4* dh = (uint4*)(g_A16 + (size_t)n*KK2);
    #pragma unroll
    for (int i = 0; i < 6; i++) dh[i] = ((uint4*)hb)[i];

    float* gd = g_gd + b*FINs;
    red4(gd+0,  x0); red4(gd+4,  x1); red4(gd+8,  x2); red4(gd+12, x3); red4(gd+16, de);
    float* gc = g_gc + b*FINs;
    red4(gc+0, x0f); red4(gc+4, x1f); red4(gc+8, x2f); red4(gc+12, x3f); red4(gc+16, cf);
}

// ---------------- per-graph offset Cg (+ zero g_acc) ----------------
__global__ void k_cg(const float* __restrict__ ke, const float* __restrict__ be) {
    int idx = blockIdx.x * 256 + threadIdx.x;            // BB*MHs = 262144
    if (idx >= BB*MHs) return;
    g_acc[idx] = 0.f;
    int b = idx >> 11;
    int mh = idx & 2047;
    int m = mh >> 5, h = mh & 31;
    float fac = g_fact[b];
    const float* k1 = ke + ((m*5 + 1)*HHs + h)*FINs;
    const float* k4 = ke + ((m*5 + 4)*HHs + h)*FINs;
    const float* gd = g_gd + b*FINs;
    const float* gc = g_gc + b*FINs;
    float s1 = 0.f, s4 = 0.f;
    #pragma unroll
    for (int f = 0; f < FINs; f++) { s1 += gd[f]*k1[f]; s4 += gc[f]*k4[f]; }
    g_Cg[idx] = be[mh] + fac*s1 + fac*fac*s4;
}

// ---------------- mma.sync GEMM + ReLU + per-graph reduction ----------------
// grid (16 mh-tiles, 391 node-tiles), 256 threads (8 warps, 4x2).
// D[128n x 128mh], K=48, single fp16: A16*W16.
__global__ __launch_bounds__(256, 2) void k_mm(const int* __restrict__ batch) {
    extern __shared__ char smem[];
    uint32_t sb = s2u(smem);
    int tid = threadIdx.x;
    int lane = tid & 31, warp = tid >> 5;
    int warpM = warp & 3, warpN = warp >> 2;
    int mb = blockIdx.x * 128, nb = blockIdx.y * 128;

    // ---- load 2 operand tiles into smem (row pitch 112B, 96B real) ----
    {
        int r = tid >> 1, half = tid & 1;
        const uint4* Ah = (const uint4*)(g_A16 + (size_t)(nb + r)*KK2) + half*3;
        const uint4* Wh = (const uint4*)(g_W16 + (size_t)(mb + r)*KK2) + half*3;
        char* base = smem + r*TPITCHB + half*48;
        #pragma unroll
        for (int i = 0; i < 3; i++) {
            *(uint4*)(base + SM_A + i*16) = Ah[i];
            *(uint4*)(base + SM_W + i*16) = Wh[i];
        }
    }
    __syncthreads();

    float c[2][8][4];
    #pragma unroll
    for (int i = 0; i < 2; i++)
        #pragma unroll
        for (int j = 0; j < 8; j++)
            #pragma unroll
            for (int q = 0; q < 4; q++) c[i][j][q] = 0.f;

    // ldmatrix per-lane address components
    int g8 = lane >> 3, l7 = lane & 7;
    int arow = ((g8 & 1) << 3) + l7;           // 0..15
    int aoff = (g8 >> 1) << 4;                 // 0 / 16 bytes
    int brow = ((g8 >> 1) << 3) + l7;
    int boff = (g8 & 1) << 4;
    uint32_t aA = sb + SM_A + (warpM*32 + arow)*TPITCHB + aoff;
    uint32_t bW = sb + SM_W + (warpN*64 + brow)*TPITCHB + boff;

    #pragma unroll
    for (int k = 0; k < 3; k++) {
        int kb = k * 32;                       // 16 k-elems = 32 bytes
        uint32_t a[2][4];
        #pragma unroll
        for (int i = 0; i < 2; i++)
            LDM4(a[i], aA + i*16*TPITCHB + kb);
        #pragma unroll
        for (int jj = 0; jj < 4; jj++) {
            uint32_t bh[4];
            LDM4(bh, bW + jj*16*TPITCHB + kb);
            #pragma unroll
            for (int i = 0; i < 2; i++) {
                mma16816(c[i][jj*2],   a[i], bh[0], bh[1]);
                mma16816(c[i][jj*2+1], a[i], bh[2], bh[3]);
            }
        }
    }
    __syncthreads();   // operand smem dead; reuse for epilogue

    // ---- epilogue: relu(C + Cg) -> buf, per-graph column sums ----
    int g0 = batch[nb];
    int nlast = nb + 127; if (nlast >= NN) nlast = NN - 1;
    int glast = batch[nlast];
    int*   flg = (int*)smem;                   // [128]
    float* cgs = (float*)(smem + 512);         // [2][128]
    float* buf = (float*)(smem + 2048);        // [128][BUFW]
    if (tid < 128) {
        int n = nb + tid;
        flg[tid] = (n < NN && batch[n] != g0) ? 1 : 0;
    } else {
        int t = tid - 128;
        cgs[t]       = g_Cg[(size_t)g0   *MHs + mb + t];
        cgs[128 + t] = g_Cg[(size_t)glast*MHs + mb + t];
    }
    __syncthreads();

    #pragma unroll
    for (int i = 0; i < 2; i++) {
        int ra = warpM*32 + i*16 + (lane >> 2);
        int rb = ra + 8;
        bool va = (nb + ra) < NN, vb = (nb + rb) < NN;
        const float* ca = cgs + flg[ra]*128;
        const float* cb = cgs + flg[rb]*128;
        #pragma unroll
        for (int j = 0; j < 8; j++) {
            int col = warpN*64 + j*8 + (lane & 3)*2;
            float2 v0, v1;
            v0.x = va ? fmaxf(c[i][j][0] + ca[col],   0.f) : 0.f;
            v0.y = va ? fmaxf(c[i][j][1] + ca[col+1], 0.f) : 0.f;
            v1.x = vb ? fmaxf(c[i][j][2] + cb[col],   0.f) : 0.f;
            v1.y = vb ? fmaxf(c[i][j][3] + cb[col+1], 0.f) : 0.f;
            *(float2*)(buf + (size_t)ra*BUFW + col) = v0;
            *(float2*)(buf + (size_t)rb*BUFW + col) = v1;
        }
    }
    __syncthreads();

    {
        int col = tid & 127, half = tid >> 7;
        float s0 = 0.f, s1 = 0.f;
        int r0 = half * 64;
        #pragma unroll 8
        for (int r = r0; r < r0 + 64; r++) {
            float v = buf[(size_t)r*BUFW + col];
            if (flg[r]) s1 += v; else s0 += v;
        }
        atomicAdd(&g_acc[(size_t)g0*MHs + mb + col], s0);
        if (glast != g0) atomicAdd(&g_acc[(size_t)glast*MHs + mb + col], s1);
    }
}

// ---------------- final ----------------
__global__ void k_final(const float* __restrict__ be, const float* __restrict__ kinv,
                        float* __restrict__ out) {
    int b = blockIdx.x;
    int m = threadIdx.x;
    float fac = g_fact[b];
    const float* acc = g_acc + (size_t)b*MHs + m*HHs;
    const float* beh = be + m*HHs;
    const float* kv  = kinv + m*HHs;
    float s = 0.f;
    #pragma unroll
    for (int h = 0; h < HHs; h++)
        s += (acc[h]*fac - fmaxf(beh[h], 0.f)) * kv[h];
    out[b*MMs + m] = s;
}

extern "C" void kernel_launch(void* const* d_in, const int* in_sizes, int n_in,
                              void* d_out, int out_size) {
    const float* x    = (const float*)d_in[0];
    const float* ea   = (const float*)d_in[1];
    const float* ke   = (const float*)d_in[2];
    const float* kinv = (const float*)d_in[3];
    const float* be   = (const float*)d_in[4];
    // d_in[5] = bias_inv: cancels in psi - zerograph
    const int* ei     = (const int*)d_in[6];
    const int* batch  = (const int*)d_in[7];
    float* out = (float*)d_out;

    cudaFuncSetAttribute(k_mm, cudaFuncAttributeMaxDynamicSharedMemorySize, SMEM_BYTES);

    k_init<<<1024, 256>>>(ke);
    k_countfact<<<1, 1024>>>(batch);
    k_edge<<<(EE+255)/256, 256>>>(ei, ea);
    k_node<<<(NN+255)/256, 256>>>(x, ea, batch);
    k_cg<<<(BB*MHs)/256, 256>>>(ke, be);
    dim3 gg(MHs/128, NTILES);
    k_mm<<<gg, 256, SMEM_BYTES>>>(batch);
    k_final<<<BB, MMs>>>(be, kinv, out);
}